// round 7
// baseline (speedup 1.0000x reference)
#include <cuda_runtime.h>

#define B_    4
#define C_    256
#define S_    1024
#define HEADS_ 8
#define D_    32
#define EPS_  1e-5f
#define KK2   0.2550635236562097f   // (1/sqrt(32)) * log2(e)

typedef unsigned long long u64;

// Scratch
__device__ float g_qkv[B_ * 3 * C_ * S_];       // [b][768][1024] (Q,K used)
__device__ float g_vt[B_ * HEADS_ * S_ * D_];   // [bh][s][d]  (V transposed)
__device__ float g_att[B_ * C_ * S_];           // [b][256][1024]
__device__ float g_coefA[B_ * C_];
__device__ float g_coefB[B_ * C_];

// ---------------------------------------------------------------------------
// f32x2 helpers
// ---------------------------------------------------------------------------
__device__ __forceinline__ u64 pk2(float lo, float hi) {
    u64 r; asm("mov.b64 %0, {%1, %2};" : "=l"(r) : "f"(lo), "f"(hi)); return r;
}
__device__ __forceinline__ void upk2(float& lo, float& hi, u64 v) {
    asm("mov.b64 {%0, %1}, %2;" : "=f"(lo), "=f"(hi) : "l"(v));
}
__device__ __forceinline__ void fma2(u64& d, u64 a, u64 b) {
    asm("fma.rn.f32x2 %0, %1, %2, %0;" : "+l"(d) : "l"(a), "l"(b));
}
__device__ __forceinline__ void mul2(u64& d, u64 a) {
    asm("mul.rn.f32x2 %0, %1, %0;" : "+l"(d) : "l"(a));
}
__device__ __forceinline__ float ex2(float x) {
    float r; asm("ex2.approx.ftz.f32 %0, %1;" : "=f"(r) : "f"(x)); return r;
}

// ---------------------------------------------------------------------------
// GroupNorm stats -> per-channel affine coefficients
// ---------------------------------------------------------------------------
__global__ __launch_bounds__(256) void gnstat_kernel(
    const float* __restrict__ x, const float* __restrict__ gamma,
    const float* __restrict__ beta) {
    int bg = blockIdx.x;
    int b = bg >> 5, g = bg & 31;
    const float4* x4 = (const float4*)(x + ((size_t)b * C_ + g * 8) * S_);
    int tid = threadIdx.x;
    float s0 = 0.f, s1 = 0.f;
    #pragma unroll
    for (int i = tid; i < 2048; i += 256) {
        float4 v = x4[i];
        s0 += v.x + v.y + v.z + v.w;
        s1 += v.x * v.x + v.y * v.y + v.z * v.z + v.w * v.w;
    }
    __shared__ float r0[256], r1[256];
    r0[tid] = s0; r1[tid] = s1;
    __syncthreads();
    for (int s = 128; s > 0; s >>= 1) {
        if (tid < s) { r0[tid] += r0[tid + s]; r1[tid] += r1[tid + s]; }
        __syncthreads();
    }
    if (tid < 8) {
        float m = r0[0] * (1.f / 8192.f);
        float var = r1[0] * (1.f / 8192.f) - m * m;
        float inv = rsqrtf(var + EPS_);
        int c = g * 8 + tid;
        float ga = gamma[c] * inv;
        g_coefA[b * C_ + c] = ga;
        g_coefB[b * C_ + c] = beta[c] - m * ga;
    }
}

// ---------------------------------------------------------------------------
// f32x2 GEMM, register-prefetch double buffer. BN=64, BK=16, 256 threads.
// VT: rows m>=512 (the V third of QKV) are written transposed to g_vt[bh][s][d].
// ---------------------------------------------------------------------------
template <int BM, int RM, bool PROJ, bool AFFINE, bool VT>
__global__ __launch_bounds__(256, 2) void gemm_f2(
    const float* __restrict__ W, const float* __restrict__ X,
    float* __restrict__ Out,
    const float* __restrict__ bias, const float* __restrict__ resid,
    int M, int K) {
    __shared__ float As[16][BM + 4];
    __shared__ float Bs[16][64];
    const int NA = BM / 64;

    int b = blockIdx.z;
    int m0 = blockIdx.y * BM;
    int n0 = blockIdx.x * 64;
    const float* Xb = X + (size_t)b * K * S_;
    const float* cA = AFFINE ? (g_coefA + b * C_) : nullptr;
    const float* cB = AFFINE ? (g_coefB + b * C_) : nullptr;
    int tid = threadIdx.x;
    int rg = tid >> 4, cg = tid & 15;
    int brow = tid >> 4, bn4 = (tid & 15) * 4;

    float4 pa[NA], pb;
    #pragma unroll
    for (int t = 0; t < NA; t++) {
        int idx = tid + t * 256;
        int row = idx >> 2, kq = (idx & 3) * 4;
        pa[t] = *(const float4*)&W[(size_t)(m0 + row) * K + kq];
    }
    pb = *(const float4*)&Xb[(size_t)brow * S_ + n0 + bn4];

    u64 acc[RM][2] = {};
    const int NCH = K / 16;

    for (int ch = 0; ch < NCH; ch++) {
        #pragma unroll
        for (int t = 0; t < NA; t++) {
            int idx = tid + t * 256;
            int row = idx >> 2, kq = (idx & 3) * 4;
            As[kq + 0][row] = pa[t].x; As[kq + 1][row] = pa[t].y;
            As[kq + 2][row] = pa[t].z; As[kq + 3][row] = pa[t].w;
        }
        {
            float4 v = pb;
            if (AFFINE) {
                int c = ch * 16 + brow;
                float a = cA[c], be = cB[c];
                v.x = fmaf(v.x, a, be); v.y = fmaf(v.y, a, be);
                v.z = fmaf(v.z, a, be); v.w = fmaf(v.w, a, be);
            }
            *(float4*)&Bs[brow][bn4] = v;
        }
        __syncthreads();
        if (ch + 1 < NCH) {
            #pragma unroll
            for (int t = 0; t < NA; t++) {
                int idx = tid + t * 256;
                int row = idx >> 2, kq = (idx & 3) * 4;
                pa[t] = *(const float4*)&W[(size_t)(m0 + row) * K + (ch + 1) * 16 + kq];
            }
            pb = *(const float4*)&Xb[(size_t)((ch + 1) * 16 + brow) * S_ + n0 + bn4];
        }
        #pragma unroll
        for (int k = 0; k < 16; k++) {
            float4 bv = *(float4*)&Bs[k][cg * 4];
            u64 bp0 = pk2(bv.x, bv.y), bp1 = pk2(bv.z, bv.w);
            float a[RM];
            #pragma unroll
            for (int t = 0; t < RM / 4; t++) {
                float4 av = *(float4*)&As[k][rg * RM + t * 4];
                a[t * 4 + 0] = av.x; a[t * 4 + 1] = av.y;
                a[t * 4 + 2] = av.z; a[t * 4 + 3] = av.w;
            }
            #pragma unroll
            for (int i = 0; i < RM; i++) {
                u64 ab = pk2(a[i], a[i]);
                fma2(acc[i][0], ab, bp0);
                fma2(acc[i][1], ab, bp1);
            }
        }
        __syncthreads();
    }

    if constexpr (VT) {
        if (m0 >= 512) {
            float o[RM][4];
            #pragma unroll
            for (int i = 0; i < RM; i++) {
                upk2(o[i][0], o[i][1], acc[i][0]);
                upk2(o[i][2], o[i][3], acc[i][1]);
            }
            int mb = m0 - 512 + rg * RM;        // 0..255
            int h = mb >> 5, db = mb & 31;
            float* vdst = g_vt + (size_t)(b * 8 + h) * 1024 * 32;
            #pragma unroll
            for (int u = 0; u < 4; u++) {
                int s = n0 + cg * 4 + u;
                *(float4*)&vdst[(size_t)s * 32 + db] =
                    make_float4(o[0][u], o[1][u], o[2][u], o[3][u]);
                *(float4*)&vdst[(size_t)s * 32 + db + 4] =
                    make_float4(o[4][u], o[5][u], o[6][u], o[7][u]);
            }
            return;
        }
    }

    #pragma unroll
    for (int i = 0; i < RM; i++) {
        int m = m0 + rg * RM + i;
        float bia = PROJ ? bias[m] : 0.f;
        #pragma unroll
        for (int jp = 0; jp < 2; jp++) {
            float lo, hi;
            upk2(lo, hi, acc[i][jp]);
            int n = n0 + cg * 4 + jp * 2;
            size_t o = ((size_t)b * M + m) * S_ + n;
            lo += bia; hi += bia;
            if (PROJ) { lo += resid[o]; hi += resid[o + 1]; }
            Out[o] = lo; Out[o + 1] = hi;
        }
    }
}

// ---------------------------------------------------------------------------
// Fused flash attention. 512 threads, BQ=128, double-buffered K/V tiles.
// QK microtile: 4i x 8j with CONTIGUOUS j-block (cj0 = cg*8): K loads are
// 2x LDS.128 per d instead of 8 scalar LDS.32.
// PV: 4i x 4d (d-pairs), 2-way j-split, smem reduction at end.
// ---------------------------------------------------------------------------
#define FL_QS   0
#define FL_KS0  4224
#define FL_KS1  8448
#define FL_VT0  12672
#define FL_VT1  17280
#define FL_PS   21888
#define FL_MX   38784
#define FL_SL   38912
#define FL_SC   39040
#define FL_TOT  39168

__global__ __launch_bounds__(512, 1) void flash_kernel() {
    extern __shared__ float sh[];
    float* Qs  = sh + FL_QS;
    float* Ps  = sh + FL_PS;
    float* smx = sh + FL_MX;
    float* sl  = sh + FL_SL;
    float* sc  = sh + FL_SC;

    int tid = threadIdx.x;
    int bh = blockIdx.y, b = bh >> 3, h = bh & 7;
    int i0 = blockIdx.x * 128;
    const float* qb  = g_qkv + ((size_t)(b * 768 + h * 32)) * 1024;
    const float* kb  = g_qkv + ((size_t)(b * 768 + 256 + h * 32)) * 1024;
    const float* vtg = g_vt + (size_t)bh * 1024 * 32;

    #pragma unroll
    for (int t = 0; t < 2; t++) {
        int idx = tid + t * 512;
        int d = idx >> 5, c4 = (idx & 31) * 4;
        *(float4*)&Qs[d * 132 + c4] = *(const float4*)(qb + (size_t)d * 1024 + i0 + c4);
    }
    if (tid < 128) { smx[tid] = -1e30f; sl[tid] = 0.f; }

    const int rg = tid >> 4, cg = tid & 15, ri0 = rg * 4;
    const int cj0 = cg * 8;                    // contiguous 8-col block
    const int jhalf = tid >> 8, t8 = tid & 255;
    const int ig = t8 >> 3, dg = t8 & 7, ri = ig * 4, d0 = dg * 4;

    float4 pfk[2], pfv[2];
    #pragma unroll
    for (int t = 0; t < 2; t++) {
        int idx = tid + t * 512;
        pfk[t] = *(const float4*)(kb + (size_t)(idx >> 5) * 1024 + (idx & 31) * 4);
        pfv[t] = *(const float4*)(vtg + (size_t)(idx >> 3) * 32 + (idx & 7) * 4);
    }

    u64 Oa[4][2] = {};

    for (int jt = 0; jt < 8; jt++) {
        float* Ks = sh + ((jt & 1) ? FL_KS1 : FL_KS0);
        float* Vt = sh + ((jt & 1) ? FL_VT1 : FL_VT0);
        #pragma unroll
        for (int t = 0; t < 2; t++) {
            int idx = tid + t * 512;
            *(float4*)&Ks[(idx >> 5) * 132 + (idx & 31) * 4] = pfk[t];
            *(float4*)&Vt[(idx >> 3) * 36 + (idx & 7) * 4]   = pfv[t];
        }
        __syncthreads();
        if (jt < 7) {
            int j1 = (jt + 1) * 128;
            #pragma unroll
            for (int t = 0; t < 2; t++) {
                int idx = tid + t * 512;
                pfk[t] = *(const float4*)(kb + (size_t)(idx >> 5) * 1024 + j1 + (idx & 31) * 4);
                pfv[t] = *(const float4*)(vtg + (size_t)(j1 + (idx >> 3)) * 32 + (idx & 7) * 4);
            }
        }

        // --- QK^T : all-vector smem loads ---
        u64 qk[2][8] = {};
        #pragma unroll
        for (int d = 0; d < 32; d++) {
            float4 q = *(float4*)&Qs[d * 132 + ri0];
            u64 q01 = pk2(q.x, q.y), q23 = pk2(q.z, q.w);
            float4 k0 = *(float4*)&Ks[d * 132 + cj0];
            float4 k1 = *(float4*)&Ks[d * 132 + cj0 + 4];
            float kk[8] = { k0.x, k0.y, k0.z, k0.w, k1.x, k1.y, k1.z, k1.w };
            #pragma unroll
            for (int jj = 0; jj < 8; jj++) {
                u64 kp = pk2(kk[jj], kk[jj]);
                fma2(qk[0][jj], q01, kp);
                fma2(qk[1][jj], q23, kp);
            }
        }
        float s[4][8];
        #pragma unroll
        for (int jj = 0; jj < 8; jj++) {
            upk2(s[0][jj], s[1][jj], qk[0][jj]);
            upk2(s[2][jj], s[3][jj], qk[1][jj]);
        }

        // --- online softmax (4 rows/thread, reduce across 16 cg lanes) ---
        float mold[4], mnew[4], rsum[4];
        #pragma unroll
        for (int ii = 0; ii < 4; ii++) {
            float mx = s[ii][0];
            #pragma unroll
            for (int jj = 1; jj < 8; jj++) mx = fmaxf(mx, s[ii][jj]);
            #pragma unroll
            for (int msk = 1; msk < 16; msk <<= 1)
                mx = fmaxf(mx, __shfl_xor_sync(0xffffffffu, mx, msk));
            mold[ii] = smx[ri0 + ii];
            mnew[ii] = fmaxf(mold[ii], mx);
            float nk = -mnew[ii] * KK2;
            float r = 0.f;
            #pragma unroll
            for (int jj = 0; jj < 8; jj++) {
                float p = ex2(fmaf(s[ii][jj], KK2, nk));
                s[ii][jj] = p;
                r += p;
            }
            #pragma unroll
            for (int msk = 1; msk < 16; msk <<= 1)
                r += __shfl_xor_sync(0xffffffffu, r, msk);
            rsum[ii] = r;
        }
        if (cg == 0) {
            #pragma unroll
            for (int ii = 0; ii < 4; ii++) {
                float c = ex2((mold[ii] - mnew[ii]) * KK2);
                sc[ri0 + ii] = c;
                smx[ri0 + ii] = mnew[ii];
                sl[ri0 + ii] = sl[ri0 + ii] * c + rsum[ii];
            }
        }
        // store P j-major: Ps[col][i], col = cj0 + jj
        #pragma unroll
        for (int jj = 0; jj < 8; jj++) {
            int col = cj0 + jj;
            *(float4*)&Ps[col * 132 + ri0] =
                make_float4(s[0][jj], s[1][jj], s[2][jj], s[3][jj]);
        }
        __syncthreads();

        // --- P @ V (this thread's j half) ---
        #pragma unroll
        for (int ii = 0; ii < 4; ii++) {
            float cc = sc[ri + ii];
            u64 cb = pk2(cc, cc);
            mul2(Oa[ii][0], cb);
            mul2(Oa[ii][1], cb);
        }
        int jb = jhalf * 64;
        #pragma unroll 4
        for (int jo = 0; jo < 64; jo++) {
            int j = jb + jo;
            float4 p = *(float4*)&Ps[j * 132 + ri];
            float4 v = *(float4*)&Vt[j * 36 + d0];
            u64 v01 = pk2(v.x, v.y), v23 = pk2(v.z, v.w);
            u64 pbx;
            pbx = pk2(p.x, p.x); fma2(Oa[0][0], pbx, v01); fma2(Oa[0][1], pbx, v23);
            pbx = pk2(p.y, p.y); fma2(Oa[1][0], pbx, v01); fma2(Oa[1][1], pbx, v23);
            pbx = pk2(p.z, p.z); fma2(Oa[2][0], pbx, v01); fma2(Oa[2][1], pbx, v23);
            pbx = pk2(p.w, p.w); fma2(Oa[3][0], pbx, v01); fma2(Oa[3][1], pbx, v23);
        }
    }
    __syncthreads();

    float o[4][4];
    #pragma unroll
    for (int ii = 0; ii < 4; ii++) {
        upk2(o[ii][0], o[ii][1], Oa[ii][0]);
        upk2(o[ii][2], o[ii][3], Oa[ii][1]);
    }
    if (jhalf == 1) {
        #pragma unroll
        for (int ii = 0; ii < 4; ii++)
            *(float4*)&Ps[(ri + ii) * 132 + d0] =
                make_float4(o[ii][0], o[ii][1], o[ii][2], o[ii][3]);
    }
    __syncthreads();
    if (jhalf == 0) {
        float* ob = g_att + ((size_t)(b * 256 + h * 32)) * 1024 + i0;
        #pragma unroll
        for (int ii = 0; ii < 4; ii++) {
            float4 part = *(float4*)&Ps[(ri + ii) * 132 + d0];
            float linv = 1.f / sl[ri + ii];
            o[ii][0] = (o[ii][0] + part.x) * linv;
            o[ii][1] = (o[ii][1] + part.y) * linv;
            o[ii][2] = (o[ii][2] + part.z) * linv;
            o[ii][3] = (o[ii][3] + part.w) * linv;
        }
        #pragma unroll
        for (int dd = 0; dd < 4; dd++)
            *(float4*)&ob[(size_t)(d0 + dd) * 1024 + ri] =
                make_float4(o[0][dd], o[1][dd], o[2][dd], o[3][dd]);
    }
}

// ---------------------------------------------------------------------------
extern "C" void kernel_launch(void* const* d_in, const int* in_sizes, int n_in,
                              void* d_out, int out_size) {
    const float* x      = (const float*)d_in[0];
    const float* gamma  = (const float*)d_in[1];
    const float* beta   = (const float*)d_in[2];
    const float* w_qkv  = (const float*)d_in[3];
    const float* w_proj = (const float*)d_in[4];
    const float* b_proj = (const float*)d_in[5];
    float* out = (float*)d_out;

    float* qkv; cudaGetSymbolAddress((void**)&qkv, g_qkv);
    float* att; cudaGetSymbolAddress((void**)&att, g_att);

    static int smem_set = 0;
    const int FLASH_SMEM = FL_TOT * 4;
    if (!smem_set) {
        cudaFuncSetAttribute(flash_kernel,
                             cudaFuncAttributeMaxDynamicSharedMemorySize,
                             FLASH_SMEM);
        smem_set = 1;
    }

    // 1. GroupNorm stats -> affine coefficients
    gnstat_kernel<<<B_ * 32, 256>>>(x, gamma, beta);

    // 2. QKV GEMM (fused GN affine; V written transposed to g_vt)
    {
        dim3 grid(S_ / 64, (3 * C_) / 128, B_);
        gemm_f2<128, 8, false, true, true><<<grid, 256>>>(
            w_qkv, x, qkv, nullptr, nullptr, 3 * C_, C_);
    }

    // 3. Fused flash attention
    {
        dim3 grid(S_ / 128, B_ * HEADS_);
        flash_kernel<<<grid, 512, FLASH_SMEM>>>();
    }

    // 4. Proj + bias + residual
    {
        dim3 grid(S_ / 64, C_ / 64, B_);
        gemm_f2<64, 4, true, false, false><<<grid, 256>>>(
            w_proj, att, out, b_proj, x, C_, C_);
    }
}

// round 9
// speedup vs baseline: 1.3416x; 1.3416x over previous
#include <cuda_runtime.h>
#include <cstdint>

#define B_    4
#define C_    256
#define S_    1024
#define HEADS_ 8
#define D_    32
#define EPS_  1e-5f
#define KK2   0.2550635236562097f   // (1/sqrt(32)) * log2(e)

typedef unsigned long long u64;

// Scratch
__device__ float g_qkv[B_ * 3 * C_ * S_];       // [b][768][1024] (Q,K used)
__device__ float g_vt[B_ * HEADS_ * S_ * D_];   // [bh][s][d]  (V transposed)
__device__ float g_att[B_ * C_ * S_];           // [b][256][1024]
__device__ float g_coefA[B_ * C_];
__device__ float g_coefB[B_ * C_];

// ---------------------------------------------------------------------------
// helpers
// ---------------------------------------------------------------------------
__device__ __forceinline__ u64 pk2(float lo, float hi) {
    u64 r; asm("mov.b64 %0, {%1, %2};" : "=l"(r) : "f"(lo), "f"(hi)); return r;
}
__device__ __forceinline__ void upk2(float& lo, float& hi, u64 v) {
    asm("mov.b64 {%0, %1}, %2;" : "=f"(lo), "=f"(hi) : "l"(v));
}
__device__ __forceinline__ void fma2(u64& d, u64 a, u64 b) {
    asm("fma.rn.f32x2 %0, %1, %2, %0;" : "+l"(d) : "l"(a), "l"(b));
}
__device__ __forceinline__ void mul2(u64& d, u64 a) {
    asm("mul.rn.f32x2 %0, %1, %0;" : "+l"(d) : "l"(a));
}
__device__ __forceinline__ float ex2(float x) {
    float r; asm("ex2.approx.ftz.f32 %0, %1;" : "=f"(r) : "f"(x)); return r;
}
__device__ __forceinline__ uint32_t smem_u32(const void* p) {
    uint32_t a;
    asm("{ .reg .u64 t; cvta.to.shared.u64 t, %1; cvt.u32.u64 %0, t; }"
        : "=r"(a) : "l"(p));
    return a;
}
__device__ __forceinline__ void cpa16(uint32_t dst, const void* src) {
    asm volatile("cp.async.ca.shared.global [%0], [%1], 16;"
                 :: "r"(dst), "l"(src) : "memory");
}
#define CPA_COMMIT() asm volatile("cp.async.commit_group;" ::: "memory")
#define CPA_WAIT0()  asm volatile("cp.async.wait_group 0;" ::: "memory")

// ---------------------------------------------------------------------------
// GroupNorm stats -> per-channel affine coefficients
// ---------------------------------------------------------------------------
__global__ __launch_bounds__(256) void gnstat_kernel(
    const float* __restrict__ x, const float* __restrict__ gamma,
    const float* __restrict__ beta) {
    int bg = blockIdx.x;
    int b = bg >> 5, g = bg & 31;
    const float4* x4 = (const float4*)(x + ((size_t)b * C_ + g * 8) * S_);
    int tid = threadIdx.x;
    float s0 = 0.f, s1 = 0.f;
    #pragma unroll
    for (int i = tid; i < 2048; i += 256) {
        float4 v = x4[i];
        s0 += v.x + v.y + v.z + v.w;
        s1 += v.x * v.x + v.y * v.y + v.z * v.z + v.w * v.w;
    }
    __shared__ float r0[256], r1[256];
    r0[tid] = s0; r1[tid] = s1;
    __syncthreads();
    for (int s = 128; s > 0; s >>= 1) {
        if (tid < s) { r0[tid] += r0[tid + s]; r1[tid] += r1[tid + s]; }
        __syncthreads();
    }
    if (tid < 8) {
        float m = r0[0] * (1.f / 8192.f);
        float var = r1[0] * (1.f / 8192.f) - m * m;
        float inv = rsqrtf(var + EPS_);
        int c = g * 8 + tid;
        float ga = gamma[c] * inv;
        g_coefA[b * C_ + c] = ga;
        g_coefB[b * C_ + c] = beta[c] - m * ga;
    }
}

// ---------------------------------------------------------------------------
// f32x2 GEMM, register-prefetch double buffer. BN=64, BK=16, 256 threads.
// VT: rows m>=512 (the V third of QKV) are written transposed to g_vt[bh][s][d].
// ---------------------------------------------------------------------------
template <int BM, int RM, bool PROJ, bool AFFINE, bool VT>
__global__ __launch_bounds__(256, 2) void gemm_f2(
    const float* __restrict__ W, const float* __restrict__ X,
    float* __restrict__ Out,
    const float* __restrict__ bias, const float* __restrict__ resid,
    int M, int K) {
    __shared__ float As[16][BM + 4];
    __shared__ float Bs[16][64];
    const int NA = BM / 64;

    int b = blockIdx.z;
    int m0 = blockIdx.y * BM;
    int n0 = blockIdx.x * 64;
    const float* Xb = X + (size_t)b * K * S_;
    const float* cA = AFFINE ? (g_coefA + b * C_) : nullptr;
    const float* cB = AFFINE ? (g_coefB + b * C_) : nullptr;
    int tid = threadIdx.x;
    int rg = tid >> 4, cg = tid & 15;
    int brow = tid >> 4, bn4 = (tid & 15) * 4;

    float4 pa[NA], pb;
    #pragma unroll
    for (int t = 0; t < NA; t++) {
        int idx = tid + t * 256;
        int row = idx >> 2, kq = (idx & 3) * 4;
        pa[t] = *(const float4*)&W[(size_t)(m0 + row) * K + kq];
    }
    pb = *(const float4*)&Xb[(size_t)brow * S_ + n0 + bn4];

    u64 acc[RM][2] = {};
    const int NCH = K / 16;

    for (int ch = 0; ch < NCH; ch++) {
        #pragma unroll
        for (int t = 0; t < NA; t++) {
            int idx = tid + t * 256;
            int row = idx >> 2, kq = (idx & 3) * 4;
            As[kq + 0][row] = pa[t].x; As[kq + 1][row] = pa[t].y;
            As[kq + 2][row] = pa[t].z; As[kq + 3][row] = pa[t].w;
        }
        {
            float4 v = pb;
            if (AFFINE) {
                int c = ch * 16 + brow;
                float a = cA[c], be = cB[c];
                v.x = fmaf(v.x, a, be); v.y = fmaf(v.y, a, be);
                v.z = fmaf(v.z, a, be); v.w = fmaf(v.w, a, be);
            }
            *(float4*)&Bs[brow][bn4] = v;
        }
        __syncthreads();
        if (ch + 1 < NCH) {
            #pragma unroll
            for (int t = 0; t < NA; t++) {
                int idx = tid + t * 256;
                int row = idx >> 2, kq = (idx & 3) * 4;
                pa[t] = *(const float4*)&W[(size_t)(m0 + row) * K + (ch + 1) * 16 + kq];
            }
            pb = *(const float4*)&Xb[(size_t)((ch + 1) * 16 + brow) * S_ + n0 + bn4];
        }
        #pragma unroll
        for (int k = 0; k < 16; k++) {
            float4 bv = *(float4*)&Bs[k][cg * 4];
            u64 bp0 = pk2(bv.x, bv.y), bp1 = pk2(bv.z, bv.w);
            float a[RM];
            #pragma unroll
            for (int t = 0; t < RM / 4; t++) {
                float4 av = *(float4*)&As[k][rg * RM + t * 4];
                a[t * 4 + 0] = av.x; a[t * 4 + 1] = av.y;
                a[t * 4 + 2] = av.z; a[t * 4 + 3] = av.w;
            }
            #pragma unroll
            for (int i = 0; i < RM; i++) {
                u64 ab = pk2(a[i], a[i]);
                fma2(acc[i][0], ab, bp0);
                fma2(acc[i][1], ab, bp1);
            }
        }
        __syncthreads();
    }

    if constexpr (VT) {
        if (m0 >= 512) {
            float o[RM][4];
            #pragma unroll
            for (int i = 0; i < RM; i++) {
                upk2(o[i][0], o[i][1], acc[i][0]);
                upk2(o[i][2], o[i][3], acc[i][1]);
            }
            int mb = m0 - 512 + rg * RM;        // 0..255
            int h = mb >> 5, db = mb & 31;
            float* vdst = g_vt + (size_t)(b * 8 + h) * 1024 * 32;
            #pragma unroll
            for (int u = 0; u < 4; u++) {
                int s = n0 + cg * 4 + u;
                *(float4*)&vdst[(size_t)s * 32 + db] =
                    make_float4(o[0][u], o[1][u], o[2][u], o[3][u]);
                *(float4*)&vdst[(size_t)s * 32 + db + 4] =
                    make_float4(o[4][u], o[5][u], o[6][u], o[7][u]);
            }
            return;
        }
    }

    #pragma unroll
    for (int i = 0; i < RM; i++) {
        int m = m0 + rg * RM + i;
        float bia = PROJ ? bias[m] : 0.f;
        #pragma unroll
        for (int jp = 0; jp < 2; jp++) {
            float lo, hi;
            upk2(lo, hi, acc[i][jp]);
            int n = n0 + cg * 4 + jp * 2;
            size_t o = ((size_t)b * M + m) * S_ + n;
            lo += bia; hi += bia;
            if (PROJ) { lo += resid[o]; hi += resid[o + 1]; }
            Out[o] = lo; Out[o + 1] = hi;
        }
    }
}

// ---------------------------------------------------------------------------
// Fused flash attention v3: 256 threads, BQ=128.
// QK: 8i x 8j microtile. PV: 8i x 8d, 4-way j-split, reduced via Ps scratch
// (row stride 36 floats = 144 B, float4-aligned). cp.async double-buffer.
// ---------------------------------------------------------------------------
#define FL_QS   0
#define FL_KS0  4224
#define FL_KS1  8448
#define FL_VT0  12672
#define FL_VT1  17280
#define FL_PS   21888
#define FL_MX   38784
#define FL_SL   38912
#define FL_SC   39040
#define FL_TOT  39168
#define RED_STR 36
#define RED_SZ  (128 * RED_STR)   // 4608 floats per partial region

__global__ __launch_bounds__(256) void flash_kernel() {
    extern __shared__ float sh[];
    float* Qs  = sh + FL_QS;
    float* Ps  = sh + FL_PS;
    float* smx = sh + FL_MX;
    float* sl  = sh + FL_SL;
    float* sc  = sh + FL_SC;

    int tid = threadIdx.x;
    int bh = blockIdx.y, b = bh >> 3, h = bh & 7;
    int i0 = blockIdx.x * 128;
    const float* qb  = g_qkv + ((size_t)(b * 768 + h * 32)) * 1024;
    const float* kb  = g_qkv + ((size_t)(b * 768 + 256 + h * 32)) * 1024;
    const float* vtg = g_vt + (size_t)bh * 1024 * 32;

    uint32_t ksb[2] = { smem_u32(sh + FL_KS0), smem_u32(sh + FL_KS1) };
    uint32_t vtb[2] = { smem_u32(sh + FL_VT0), smem_u32(sh + FL_VT1) };

    // async-load tile 0 (K and V)
    #pragma unroll
    for (int t = 0; t < 4; t++) {
        int idx = tid + t * 256;
        int d = idx >> 5, c4 = (idx & 31) * 4;
        cpa16(ksb[0] + (d * 132 + c4) * 4, kb + (size_t)d * 1024 + c4);
        int j = idx >> 3, d4 = (idx & 7) * 4;
        cpa16(vtb[0] + (j * 36 + d4) * 4, vtg + (size_t)j * 32 + d4);
    }
    CPA_COMMIT();

    // Q tile -> smem [d][128]
    #pragma unroll
    for (int t = 0; t < 4; t++) {
        int idx = tid + t * 256;
        int d = idx >> 5, c4 = (idx & 31) * 4;
        *(float4*)&Qs[d * 132 + c4] = *(const float4*)(qb + (size_t)d * 1024 + i0 + c4);
    }
    if (tid < 128) { smx[tid] = -1e30f; sl[tid] = 0.f; }

    const int rg = tid >> 4, cg = tid & 15, ri0 = rg * 8;
    const int jgrp = tid >> 6, r6 = tid & 63;
    const int i8 = (r6 >> 2) * 8, d0 = (r6 & 3) * 8;

    u64 Oa[8][4] = {};   // 8 i-rows x 4 d-pairs

    for (int jt = 0; jt < 8; jt++) {
        float* Ks = sh + ((jt & 1) ? FL_KS1 : FL_KS0);
        float* Vt = sh + ((jt & 1) ? FL_VT1 : FL_VT0);
        CPA_WAIT0();
        __syncthreads();
        // prefetch tile jt+1 (overlaps this iteration's compute)
        if (jt < 7) {
            int j1 = (jt + 1) * 128;
            int bn = (jt + 1) & 1;
            #pragma unroll
            for (int t = 0; t < 4; t++) {
                int idx = tid + t * 256;
                int d = idx >> 5, c4 = (idx & 31) * 4;
                cpa16(ksb[bn] + (d * 132 + c4) * 4, kb + (size_t)d * 1024 + j1 + c4);
                int j = idx >> 3, d4 = (idx & 7) * 4;
                cpa16(vtb[bn] + (j * 36 + d4) * 4, vtg + (size_t)(j1 + j) * 32 + d4);
            }
            CPA_COMMIT();
        }

        // --- QK^T: 8x8 ---
        u64 qk[4][8] = {};
        #pragma unroll
        for (int d = 0; d < 32; d++) {
            float4 q0 = *(float4*)&Qs[d * 132 + ri0];
            float4 q1 = *(float4*)&Qs[d * 132 + ri0 + 4];
            u64 qp[4] = { pk2(q0.x, q0.y), pk2(q0.z, q0.w),
                          pk2(q1.x, q1.y), pk2(q1.z, q1.w) };
            #pragma unroll
            for (int jj = 0; jj < 8; jj++) {
                float kv = Ks[d * 132 + cg + 16 * jj];
                u64 kp = pk2(kv, kv);
                fma2(qk[0][jj], qp[0], kp);
                fma2(qk[1][jj], qp[1], kp);
                fma2(qk[2][jj], qp[2], kp);
                fma2(qk[3][jj], qp[3], kp);
            }
        }
        float s[8][8];
        #pragma unroll
        for (int ip = 0; ip < 4; ip++)
            #pragma unroll
            for (int jj = 0; jj < 8; jj++)
                upk2(s[2 * ip][jj], s[2 * ip + 1][jj], qk[ip][jj]);

        // --- online softmax (8 rows/thread, reduce over 16 cg lanes) ---
        float mold[8], mnew[8], rsum[8];
        #pragma unroll
        for (int ii = 0; ii < 8; ii++) {
            float mx = s[ii][0];
            #pragma unroll
            for (int jj = 1; jj < 8; jj++) mx = fmaxf(mx, s[ii][jj]);
            #pragma unroll
            for (int msk = 1; msk < 16; msk <<= 1)
                mx = fmaxf(mx, __shfl_xor_sync(0xffffffffu, mx, msk));
            mold[ii] = smx[ri0 + ii];
            mnew[ii] = fmaxf(mold[ii], mx);
            float nk = -mnew[ii] * KK2;
            float r = 0.f;
            #pragma unroll
            for (int jj = 0; jj < 8; jj++) {
                float p = ex2(fmaf(s[ii][jj], KK2, nk));
                s[ii][jj] = p;
                r += p;
            }
            #pragma unroll
            for (int msk = 1; msk < 16; msk <<= 1)
                r += __shfl_xor_sync(0xffffffffu, r, msk);
            rsum[ii] = r;
        }
        if (cg == 0) {
            #pragma unroll
            for (int ii = 0; ii < 8; ii++) {
                float c = ex2((mold[ii] - mnew[ii]) * KK2);
                sc[ri0 + ii] = c;
                smx[ri0 + ii] = mnew[ii];
                sl[ri0 + ii] = sl[ri0 + ii] * c + rsum[ii];
            }
        }
        // store P j-major (strided cols, 2-way banking)
        #pragma unroll
        for (int jj = 0; jj < 8; jj++) {
            int col = cg + 16 * jj;
            *(float4*)&Ps[col * 132 + ri0] =
                make_float4(s[0][jj], s[1][jj], s[2][jj], s[3][jj]);
            *(float4*)&Ps[col * 132 + ri0 + 4] =
                make_float4(s[4][jj], s[5][jj], s[6][jj], s[7][jj]);
        }
        __syncthreads();

        // --- P @ V: 8i x 8d over this thread's 32-j quarter ---
        #pragma unroll
        for (int ii = 0; ii < 8; ii++) {
            float cc = sc[i8 + ii];
            u64 cb = pk2(cc, cc);
            mul2(Oa[ii][0], cb); mul2(Oa[ii][1], cb);
            mul2(Oa[ii][2], cb); mul2(Oa[ii][3], cb);
        }
        int jb = jgrp * 32;
        #pragma unroll 2
        for (int jo = 0; jo < 32; jo++) {
            int j = jb + jo;
            float4 p0 = *(float4*)&Ps[j * 132 + i8];
            float4 p1 = *(float4*)&Ps[j * 132 + i8 + 4];
            float pv[8] = { p0.x, p0.y, p0.z, p0.w, p1.x, p1.y, p1.z, p1.w };
            float4 v0 = *(float4*)&Vt[j * 36 + d0];
            float4 v1 = *(float4*)&Vt[j * 36 + d0 + 4];
            u64 vp[4] = { pk2(v0.x, v0.y), pk2(v0.z, v0.w),
                          pk2(v1.x, v1.y), pk2(v1.z, v1.w) };
            #pragma unroll
            for (int ii = 0; ii < 8; ii++) {
                u64 pbx = pk2(pv[ii], pv[ii]);
                fma2(Oa[ii][0], pbx, vp[0]);
                fma2(Oa[ii][1], pbx, vp[1]);
                fma2(Oa[ii][2], pbx, vp[2]);
                fma2(Oa[ii][3], pbx, vp[3]);
            }
        }
    }
    __syncthreads();

    // 4-way partial reduce via Ps scratch (stride-36 rows, 16B aligned)
    float o[8][8];
    #pragma unroll
    for (int ii = 0; ii < 8; ii++) {
        upk2(o[ii][0], o[ii][1], Oa[ii][0]);
        upk2(o[ii][2], o[ii][3], Oa[ii][1]);
        upk2(o[ii][4], o[ii][5], Oa[ii][2]);
        upk2(o[ii][6], o[ii][7], Oa[ii][3]);
    }
    if (jgrp > 0) {
        float* dst = Ps + (jgrp - 1) * RED_SZ;
        #pragma unroll
        for (int ii = 0; ii < 8; ii++) {
            *(float4*)&dst[(i8 + ii) * RED_STR + d0] =
                make_float4(o[ii][0], o[ii][1], o[ii][2], o[ii][3]);
            *(float4*)&dst[(i8 + ii) * RED_STR + d0 + 4] =
                make_float4(o[ii][4], o[ii][5], o[ii][6], o[ii][7]);
        }
    }
    __syncthreads();
    if (jgrp == 0) {
        float* ob = g_att + ((size_t)(b * 256 + h * 32)) * 1024 + i0;
        #pragma unroll
        for (int ii = 0; ii < 8; ii++) {
            #pragma unroll
            for (int g = 0; g < 3; g++) {
                float4 pa = *(float4*)&Ps[g * RED_SZ + (i8 + ii) * RED_STR + d0];
                float4 pb2 = *(float4*)&Ps[g * RED_SZ + (i8 + ii) * RED_STR + d0 + 4];
                o[ii][0] += pa.x;  o[ii][1] += pa.y;
                o[ii][2] += pa.z;  o[ii][3] += pa.w;
                o[ii][4] += pb2.x; o[ii][5] += pb2.y;
                o[ii][6] += pb2.z; o[ii][7] += pb2.w;
            }
            float linv = 1.f / sl[i8 + ii];
            #pragma unroll
            for (int dd = 0; dd < 8; dd++) o[ii][dd] *= linv;
        }
        #pragma unroll
        for (int dd = 0; dd < 8; dd++) {
            *(float4*)&ob[(size_t)(d0 + dd) * 1024 + i8] =
                make_float4(o[0][dd], o[1][dd], o[2][dd], o[3][dd]);
            *(float4*)&ob[(size_t)(d0 + dd) * 1024 + i8 + 4] =
                make_float4(o[4][dd], o[5][dd], o[6][dd], o[7][dd]);
        }
    }
}

// ---------------------------------------------------------------------------
extern "C" void kernel_launch(void* const* d_in, const int* in_sizes, int n_in,
                              void* d_out, int out_size) {
    const float* x      = (const float*)d_in[0];
    const float* gamma  = (const float*)d_in[1];
    const float* beta   = (const float*)d_in[2];
    const float* w_qkv  = (const float*)d_in[3];
    const float* w_proj = (const float*)d_in[4];
    const float* b_proj = (const float*)d_in[5];
    float* out = (float*)d_out;

    float* qkv; cudaGetSymbolAddress((void**)&qkv, g_qkv);
    float* att; cudaGetSymbolAddress((void**)&att, g_att);

    static int smem_set = 0;
    const int FLASH_SMEM = FL_TOT * 4;
    if (!smem_set) {
        cudaFuncSetAttribute(flash_kernel,
                             cudaFuncAttributeMaxDynamicSharedMemorySize,
                             FLASH_SMEM);
        smem_set = 1;
    }

    // 1. GroupNorm stats -> affine coefficients
    gnstat_kernel<<<B_ * 32, 256>>>(x, gamma, beta);

    // 2. QKV GEMM (fused GN affine; V written transposed to g_vt)
    {
        dim3 grid(S_ / 64, (3 * C_) / 128, B_);
        gemm_f2<128, 8, false, true, true><<<grid, 256>>>(
            w_qkv, x, qkv, nullptr, nullptr, 3 * C_, C_);
    }

    // 3. Fused flash attention (256 threads, 8x8 microtiles, cp.async)
    {
        dim3 grid(S_ / 128, B_ * HEADS_);
        flash_kernel<<<grid, 256, FLASH_SMEM>>>();
    }

    // 4. Proj + bias + residual
    {
        dim3 grid(S_ / 64, C_ / 64, B_);
        gemm_f2<64, 4, true, false, false><<<grid, 256>>>(
            w_proj, att, out, b_proj, x, C_, C_);
    }
}

// round 11
// speedup vs baseline: 1.3988x; 1.0427x over previous
#include <cuda_runtime.h>
#include <cstdint>

#define B_    4
#define C_    256
#define S_    1024
#define HEADS_ 8
#define D_    32
#define EPS_  1e-5f
#define KK2   0.2550635236562097f   // (1/sqrt(32)) * log2(e)

typedef unsigned long long u64;

// Scratch
__device__ float g_qkv[B_ * 3 * C_ * S_];       // [b][768][1024] (Q,K used)
__device__ float g_vt[B_ * HEADS_ * S_ * D_];   // [bh][s][d]
__device__ float g_att[B_ * C_ * S_];           // [b][256][1024]
__device__ float g_coefA[B_ * C_];
__device__ float g_coefB[B_ * C_];
__device__ float g_w4t[B_ * C_ * 3 * C_];       // [b][k][m] = w_qkv[m][k]*cA[b][k]
__device__ float g_bias4[B_ * 3 * C_];          // [b][m]
__device__ float g_wprojT[C_ * C_];             // [k][m]

// ---------------------------------------------------------------------------
// helpers
// ---------------------------------------------------------------------------
__device__ __forceinline__ u64 pk2(float lo, float hi) {
    u64 r; asm("mov.b64 %0, {%1, %2};" : "=l"(r) : "f"(lo), "f"(hi)); return r;
}
__device__ __forceinline__ void upk2(float& lo, float& hi, u64 v) {
    asm("mov.b64 {%0, %1}, %2;" : "=f"(lo), "=f"(hi) : "l"(v));
}
__device__ __forceinline__ void fma2(u64& d, u64 a, u64 b) {
    asm("fma.rn.f32x2 %0, %1, %2, %0;" : "+l"(d) : "l"(a), "l"(b));
}
__device__ __forceinline__ void mul2(u64& d, u64 a) {
    asm("mul.rn.f32x2 %0, %1, %0;" : "+l"(d) : "l"(a));
}
__device__ __forceinline__ float ex2(float x) {
    float r; asm("ex2.approx.ftz.f32 %0, %1;" : "=f"(r) : "f"(x)); return r;
}
__device__ __forceinline__ uint32_t smem_u32(const void* p) {
    uint32_t a;
    asm("{ .reg .u64 t; cvta.to.shared.u64 t, %1; cvt.u32.u64 %0, t; }"
        : "=r"(a) : "l"(p));
    return a;
}
__device__ __forceinline__ void cpa16(uint32_t dst, const void* src) {
    asm volatile("cp.async.ca.shared.global [%0], [%1], 16;"
                 :: "r"(dst), "l"(src) : "memory");
}
#define CPA_COMMIT() asm volatile("cp.async.commit_group;" ::: "memory")
#define CPA_WAIT0()  asm volatile("cp.async.wait_group 0;" ::: "memory")
#define CPA_WAIT1()  asm volatile("cp.async.wait_group 1;" ::: "memory")

// ---------------------------------------------------------------------------
// GroupNorm stats -> per-channel affine coefficients
// ---------------------------------------------------------------------------
__global__ __launch_bounds__(256) void gnstat_kernel(
    const float* __restrict__ x, const float* __restrict__ gamma,
    const float* __restrict__ beta) {
    int bg = blockIdx.x;
    int b = bg >> 5, g = bg & 31;
    const float4* x4 = (const float4*)(x + ((size_t)b * C_ + g * 8) * S_);
    int tid = threadIdx.x;
    float s0 = 0.f, s1 = 0.f;
    #pragma unroll
    for (int i = tid; i < 2048; i += 256) {
        float4 v = x4[i];
        s0 += v.x + v.y + v.z + v.w;
        s1 += v.x * v.x + v.y * v.y + v.z * v.z + v.w * v.w;
    }
    __shared__ float r0[256], r1[256];
    r0[tid] = s0; r1[tid] = s1;
    __syncthreads();
    for (int s = 128; s > 0; s >>= 1) {
        if (tid < s) { r0[tid] += r0[tid + s]; r1[tid] += r1[tid + s]; }
        __syncthreads();
    }
    if (tid < 8) {
        float m = r0[0] * (1.f / 8192.f);
        float var = r1[0] * (1.f / 8192.f) - m * m;
        float inv = rsqrtf(var + EPS_);
        int c = g * 8 + tid;
        float ga = gamma[c] * inv;
        g_coefA[b * C_ + c] = ga;
        g_coefB[b * C_ + c] = beta[c] - m * ga;
    }
}

// ---------------------------------------------------------------------------
// Prep: W4T[b][k][m] = w_qkv[m][k] * cA[b][k]
// Staging tile stride 36 floats (144 B, 16B-aligned rows for float4 stores).
// ---------------------------------------------------------------------------
__global__ __launch_bounds__(256) void prep_wqkvT(const float* __restrict__ w) {
    __shared__ float T[32][36];
    int m0 = blockIdx.x * 32, k0 = blockIdx.y * 32, b = blockIdx.z;
    int r = threadIdx.x >> 3, c4 = (threadIdx.x & 7) * 4;
    *(float4*)&T[r][c4] = *(const float4*)&w[(size_t)(m0 + r) * C_ + k0 + c4];
    __syncthreads();
    int kk = r, m4 = c4;
    float a = g_coefA[b * C_ + k0 + kk];
    float4 o = make_float4(T[m4][kk] * a, T[m4 + 1][kk] * a,
                           T[m4 + 2][kk] * a, T[m4 + 3][kk] * a);
    *(float4*)&g_w4t[((size_t)b * C_ + k0 + kk) * (3 * C_) + m0 + m4] = o;
}

// Prep: bias4[b][m] = sum_k w_qkv[m][k] * cB[b][k]   (one warp per m)
__global__ __launch_bounds__(256) void prep_bias(const float* __restrict__ w) {
    int b = blockIdx.y;
    int m = blockIdx.x * 8 + (threadIdx.x >> 5);
    int lane = threadIdx.x & 31;
    const float* cB = g_coefB + b * C_;
    float s = 0.f;
    #pragma unroll
    for (int k = lane; k < C_; k += 32) s += w[(size_t)m * C_ + k] * cB[k];
    #pragma unroll
    for (int msk = 16; msk > 0; msk >>= 1)
        s += __shfl_xor_sync(0xffffffffu, s, msk);
    if (lane == 0) g_bias4[b * 3 * C_ + m] = s;
}

// Prep: wprojT[k][m] = w_proj[m][k]   (stride-36 staging tile)
__global__ __launch_bounds__(256) void prep_projT(const float* __restrict__ w) {
    __shared__ float T[32][36];
    int m0 = blockIdx.x * 32, k0 = blockIdx.y * 32;
    int r = threadIdx.x >> 3, c4 = (threadIdx.x & 7) * 4;
    *(float4*)&T[r][c4] = *(const float4*)&w[(size_t)(m0 + r) * C_ + k0 + c4];
    __syncthreads();
    int kk = r, m4 = c4;
    float4 o = make_float4(T[m4][kk], T[m4 + 1][kk], T[m4 + 2][kk], T[m4 + 3][kk]);
    *(float4*)&g_wprojT[(size_t)(k0 + kk) * C_ + m0 + m4] = o;
}

// ---------------------------------------------------------------------------
// cp.async pipelined GEMM (k-major weights, no transpose in hot loop).
// Out[b][m][n] = sum_k WT[k][m] * X[b][k][n] + bias[m]  (+resid for proj)
// BM x 64 tile, BK=16, 2-stage cp.async, 256 threads, 3 blocks/SM.
// QKV: rows m>=512 (V) written transposed to g_vt with bias.
// ---------------------------------------------------------------------------
template <bool QKV, int BM, int RM>
__global__ __launch_bounds__(256, 3) void gemm_cp(
    const float* __restrict__ WT, const float* __restrict__ X,
    float* __restrict__ Out, const float* __restrict__ bias,
    const float* __restrict__ resid, int M) {
    __shared__ __align__(16) float As[2][16][BM];
    __shared__ __align__(16) float Bs[2][16][64];
    const int NA = BM / 64;   // A float4 loads per thread per stage

    int tid = threadIdx.x;
    int b = blockIdx.z, m0 = blockIdx.y * BM, n0 = blockIdx.x * 64;
    const float* Wb = WT + (QKV ? (size_t)b * C_ * M : 0);
    const float* Xb = X + (size_t)b * C_ * S_;
    uint32_t aA[2] = { smem_u32(&As[0][0][0]), smem_u32(&As[1][0][0]) };
    uint32_t aB[2] = { smem_u32(&Bs[0][0][0]), smem_u32(&Bs[1][0][0]) };

#define LOADST(CH, ST) do {                                                   \
    int kb_ = (CH) * 16;                                                      \
    _Pragma("unroll")                                                         \
    for (int u_ = 0; u_ < NA; u_++) {                                         \
        int idx_ = tid + u_ * 256;                                            \
        int k_ = idx_ / (BM / 4), m4_ = (idx_ % (BM / 4)) * 4;                \
        cpa16(aA[ST] + (k_ * BM + m4_) * 4,                                   \
              Wb + (size_t)(kb_ + k_) * M + m0 + m4_);                        \
    }                                                                         \
    {                                                                         \
        int k_ = tid >> 4, n4_ = (tid & 15) * 4;                              \
        cpa16(aB[ST] + (k_ * 64 + n4_) * 4,                                   \
              Xb + (size_t)(kb_ + k_) * S_ + n0 + n4_);                       \
    }                                                                         \
} while (0)

    LOADST(0, 0); CPA_COMMIT();
    LOADST(1, 1); CPA_COMMIT();

    int rg = tid >> 4, cg = tid & 15;
    u64 acc[RM][2] = {};

    #pragma unroll
    for (int ch = 0; ch < 16; ch++) {
        int st = ch & 1;
        if (ch == 15) { CPA_WAIT0(); } else { CPA_WAIT1(); }
        __syncthreads();
        #pragma unroll
        for (int k = 0; k < 16; k++) {
            float4 bv = *(float4*)&Bs[st][k][cg * 4];
            u64 bp0 = pk2(bv.x, bv.y), bp1 = pk2(bv.z, bv.w);
            float a[RM];
            #pragma unroll
            for (int t = 0; t < RM / 4; t++) {
                float4 av = *(float4*)&As[st][k][rg * RM + t * 4];
                a[t * 4 + 0] = av.x; a[t * 4 + 1] = av.y;
                a[t * 4 + 2] = av.z; a[t * 4 + 3] = av.w;
            }
            #pragma unroll
            for (int i = 0; i < RM; i++) {
                u64 ab = pk2(a[i], a[i]);
                fma2(acc[i][0], ab, bp0);
                fma2(acc[i][1], ab, bp1);
            }
        }
        __syncthreads();
        if (ch + 2 < 16) { LOADST(ch + 2, st); CPA_COMMIT(); }
    }
#undef LOADST

    float o[RM][4];
    #pragma unroll
    for (int i = 0; i < RM; i++) {
        upk2(o[i][0], o[i][1], acc[i][0]);
        upk2(o[i][2], o[i][3], acc[i][1]);
    }

    if (QKV && m0 >= 512) {
        // V rows: add bias, store transposed to g_vt[bh][s][d]
        #pragma unroll
        for (int i = 0; i < RM; i++) {
            float bv = bias[b * M + m0 + rg * RM + i];
            #pragma unroll
            for (int u = 0; u < 4; u++) o[i][u] += bv;
        }
        int mb = m0 - 512 + rg * RM;
        int h = mb >> 5, db = mb & 31;
        float* vdst = g_vt + (size_t)(b * 8 + h) * 1024 * 32;
        #pragma unroll
        for (int u = 0; u < 4; u++) {
            int s = n0 + cg * 4 + u;
            *(float4*)&vdst[(size_t)s * 32 + db] =
                make_float4(o[0][u], o[1][u], o[2][u], o[3][u]);
            *(float4*)&vdst[(size_t)s * 32 + db + 4] =
                make_float4(o[4][u], o[5][u], o[6][u], o[7][u]);
        }
        return;
    }

    #pragma unroll
    for (int i = 0; i < RM; i++) {
        int m = m0 + rg * RM + i;
        float bv = bias[(QKV ? b * M : 0) + m];
        size_t off = ((size_t)b * M + m) * S_ + n0 + cg * 4;
        float4 v = make_float4(o[i][0] + bv, o[i][1] + bv,
                               o[i][2] + bv, o[i][3] + bv);
        if (!QKV) {
            float4 rr = *(const float4*)&resid[off];
            v.x += rr.x; v.y += rr.y; v.z += rr.z; v.w += rr.w;
        }
        *(float4*)&Out[off] = v;
    }
}

// ---------------------------------------------------------------------------
// Fused flash attention (round-9, passing). 256 threads, BQ=128.
// ---------------------------------------------------------------------------
#define FL_QS   0
#define FL_KS0  4224
#define FL_KS1  8448
#define FL_VT0  12672
#define FL_VT1  17280
#define FL_PS   21888
#define FL_MX   38784
#define FL_SL   38912
#define FL_SC   39040
#define FL_TOT  39168
#define RED_STR 36
#define RED_SZ  (128 * RED_STR)

__global__ __launch_bounds__(256) void flash_kernel() {
    extern __shared__ float sh[];
    float* Qs  = sh + FL_QS;
    float* Ps  = sh + FL_PS;
    float* smx = sh + FL_MX;
    float* sl  = sh + FL_SL;
    float* sc  = sh + FL_SC;

    int tid = threadIdx.x;
    int bh = blockIdx.y, b = bh >> 3, h = bh & 7;
    int i0 = blockIdx.x * 128;
    const float* qb  = g_qkv + ((size_t)(b * 768 + h * 32)) * 1024;
    const float* kb  = g_qkv + ((size_t)(b * 768 + 256 + h * 32)) * 1024;
    const float* vtg = g_vt + (size_t)bh * 1024 * 32;

    uint32_t ksb[2] = { smem_u32(sh + FL_KS0), smem_u32(sh + FL_KS1) };
    uint32_t vtb[2] = { smem_u32(sh + FL_VT0), smem_u32(sh + FL_VT1) };

    #pragma unroll
    for (int t = 0; t < 4; t++) {
        int idx = tid + t * 256;
        int d = idx >> 5, c4 = (idx & 31) * 4;
        cpa16(ksb[0] + (d * 132 + c4) * 4, kb + (size_t)d * 1024 + c4);
        int j = idx >> 3, d4 = (idx & 7) * 4;
        cpa16(vtb[0] + (j * 36 + d4) * 4, vtg + (size_t)j * 32 + d4);
    }
    CPA_COMMIT();

    #pragma unroll
    for (int t = 0; t < 4; t++) {
        int idx = tid + t * 256;
        int d = idx >> 5, c4 = (idx & 31) * 4;
        *(float4*)&Qs[d * 132 + c4] = *(const float4*)(qb + (size_t)d * 1024 + i0 + c4);
    }
    if (tid < 128) { smx[tid] = -1e30f; sl[tid] = 0.f; }

    const int rg = tid >> 4, cg = tid & 15, ri0 = rg * 8;
    const int jgrp = tid >> 6, r6 = tid & 63;
    const int i8 = (r6 >> 2) * 8, d0 = (r6 & 3) * 8;

    u64 Oa[8][4] = {};

    for (int jt = 0; jt < 8; jt++) {
        float* Ks = sh + ((jt & 1) ? FL_KS1 : FL_KS0);
        float* Vt = sh + ((jt & 1) ? FL_VT1 : FL_VT0);
        CPA_WAIT0();
        __syncthreads();
        if (jt < 7) {
            int j1 = (jt + 1) * 128;
            int bn = (jt + 1) & 1;
            #pragma unroll
            for (int t = 0; t < 4; t++) {
                int idx = tid + t * 256;
                int d = idx >> 5, c4 = (idx & 31) * 4;
                cpa16(ksb[bn] + (d * 132 + c4) * 4, kb + (size_t)d * 1024 + j1 + c4);
                int j = idx >> 3, d4 = (idx & 7) * 4;
                cpa16(vtb[bn] + (j * 36 + d4) * 4, vtg + (size_t)(j1 + j) * 32 + d4);
            }
            CPA_COMMIT();
        }

        u64 qk[4][8] = {};
        #pragma unroll
        for (int d = 0; d < 32; d++) {
            float4 q0 = *(float4*)&Qs[d * 132 + ri0];
            float4 q1 = *(float4*)&Qs[d * 132 + ri0 + 4];
            u64 qp[4] = { pk2(q0.x, q0.y), pk2(q0.z, q0.w),
                          pk2(q1.x, q1.y), pk2(q1.z, q1.w) };
            #pragma unroll
            for (int jj = 0; jj < 8; jj++) {
                float kv = Ks[d * 132 + cg + 16 * jj];
                u64 kp = pk2(kv, kv);
                fma2(qk[0][jj], qp[0], kp);
                fma2(qk[1][jj], qp[1], kp);
                fma2(qk[2][jj], qp[2], kp);
                fma2(qk[3][jj], qp[3], kp);
            }
        }
        float s[8][8];
        #pragma unroll
        for (int ip = 0; ip < 4; ip++)
            #pragma unroll
            for (int jj = 0; jj < 8; jj++)
                upk2(s[2 * ip][jj], s[2 * ip + 1][jj], qk[ip][jj]);

        float mold[8], mnew[8], rsum[8];
        #pragma unroll
        for (int ii = 0; ii < 8; ii++) {
            float mx = s[ii][0];
            #pragma unroll
            for (int jj = 1; jj < 8; jj++) mx = fmaxf(mx, s[ii][jj]);
            #pragma unroll
            for (int msk = 1; msk < 16; msk <<= 1)
                mx = fmaxf(mx, __shfl_xor_sync(0xffffffffu, mx, msk));
            mold[ii] = smx[ri0 + ii];
            mnew[ii] = fmaxf(mold[ii], mx);
            float nk = -mnew[ii] * KK2;
            float r = 0.f;
            #pragma unroll
            for (int jj = 0; jj < 8; jj++) {
                float p = ex2(fmaf(s[ii][jj], KK2, nk));
                s[ii][jj] = p;
                r += p;
            }
            #pragma unroll
            for (int msk = 1; msk < 16; msk <<= 1)
                r += __shfl_xor_sync(0xffffffffu, r, msk);
            rsum[ii] = r;
        }
        if (cg == 0) {
            #pragma unroll
            for (int ii = 0; ii < 8; ii++) {
                float c = ex2((mold[ii] - mnew[ii]) * KK2);
                sc[ri0 + ii] = c;
                smx[ri0 + ii] = mnew[ii];
                sl[ri0 + ii] = sl[ri0 + ii] * c + rsum[ii];
            }
        }
        #pragma unroll
        for (int jj = 0; jj < 8; jj++) {
            int col = cg + 16 * jj;
            *(float4*)&Ps[col * 132 + ri0] =
                make_float4(s[0][jj], s[1][jj], s[2][jj], s[3][jj]);
            *(float4*)&Ps[col * 132 + ri0 + 4] =
                make_float4(s[4][jj], s[5][jj], s[6][jj], s[7][jj]);
        }
        __syncthreads();

        #pragma unroll
        for (int ii = 0; ii < 8; ii++) {
            float cc = sc[i8 + ii];
            u64 cb = pk2(cc, cc);
            mul2(Oa[ii][0], cb); mul2(Oa[ii][1], cb);
            mul2(Oa[ii][2], cb); mul2(Oa[ii][3], cb);
        }
        int jb = jgrp * 32;
        #pragma unroll 2
        for (int jo = 0; jo < 32; jo++) {
            int j = jb + jo;
            float4 p0 = *(float4*)&Ps[j * 132 + i8];
            float4 p1 = *(float4*)&Ps[j * 132 + i8 + 4];
            float pv[8] = { p0.x, p0.y, p0.z, p0.w, p1.x, p1.y, p1.z, p1.w };
            float4 v0 = *(float4*)&Vt[j * 36 + d0];
            float4 v1 = *(float4*)&Vt[j * 36 + d0 + 4];
            u64 vp[4] = { pk2(v0.x, v0.y), pk2(v0.z, v0.w),
                          pk2(v1.x, v1.y), pk2(v1.z, v1.w) };
            #pragma unroll
            for (int ii = 0; ii < 8; ii++) {
                u64 pbx = pk2(pv[ii], pv[ii]);
                fma2(Oa[ii][0], pbx, vp[0]);
                fma2(Oa[ii][1], pbx, vp[1]);
                fma2(Oa[ii][2], pbx, vp[2]);
                fma2(Oa[ii][3], pbx, vp[3]);
            }
        }
    }
    __syncthreads();

    float o[8][8];
    #pragma unroll
    for (int ii = 0; ii < 8; ii++) {
        upk2(o[ii][0], o[ii][1], Oa[ii][0]);
        upk2(o[ii][2], o[ii][3], Oa[ii][1]);
        upk2(o[ii][4], o[ii][5], Oa[ii][2]);
        upk2(o[ii][6], o[ii][7], Oa[ii][3]);
    }
    if (jgrp > 0) {
        float* dst = Ps + (jgrp - 1) * RED_SZ;
        #pragma unroll
        for (int ii = 0; ii < 8; ii++) {
            *(float4*)&dst[(i8 + ii) * RED_STR + d0] =
                make_float4(o[ii][0], o[ii][1], o[ii][2], o[ii][3]);
            *(float4*)&dst[(i8 + ii) * RED_STR + d0 + 4] =
                make_float4(o[ii][4], o[ii][5], o[ii][6], o[ii][7]);
        }
    }
    __syncthreads();
    if (jgrp == 0) {
        float* ob = g_att + ((size_t)(b * 256 + h * 32)) * 1024 + i0;
        #pragma unroll
        for (int ii = 0; ii < 8; ii++) {
            #pragma unroll
            for (int g = 0; g < 3; g++) {
                float4 pa = *(float4*)&Ps[g * RED_SZ + (i8 + ii) * RED_STR + d0];
                float4 pb2 = *(float4*)&Ps[g * RED_SZ + (i8 + ii) * RED_STR + d0 + 4];
                o[ii][0] += pa.x;  o[ii][1] += pa.y;
                o[ii][2] += pa.z;  o[ii][3] += pa.w;
                o[ii][4] += pb2.x; o[ii][5] += pb2.y;
                o[ii][6] += pb2.z; o[ii][7] += pb2.w;
            }
            float linv = 1.f / sl[i8 + ii];
            #pragma unroll
            for (int dd = 0; dd < 8; dd++) o[ii][dd] *= linv;
        }
        #pragma unroll
        for (int dd = 0; dd < 8; dd++) {
            *(float4*)&ob[(size_t)(d0 + dd) * 1024 + i8] =
                make_float4(o[0][dd], o[1][dd], o[2][dd], o[3][dd]);
            *(float4*)&ob[(size_t)(d0 + dd) * 1024 + i8 + 4] =
                make_float4(o[4][dd], o[5][dd], o[6][dd], o[7][dd]);
        }
    }
}

// ---------------------------------------------------------------------------
extern "C" void kernel_launch(void* const* d_in, const int* in_sizes, int n_in,
                              void* d_out, int out_size) {
    const float* x      = (const float*)d_in[0];
    const float* gamma  = (const float*)d_in[1];
    const float* beta   = (const float*)d_in[2];
    const float* w_qkv  = (const float*)d_in[3];
    const float* w_proj = (const float*)d_in[4];
    const float* b_proj = (const float*)d_in[5];
    float* out = (float*)d_out;

    float* qkv;   cudaGetSymbolAddress((void**)&qkv, g_qkv);
    float* att;   cudaGetSymbolAddress((void**)&att, g_att);
    float* w4t;   cudaGetSymbolAddress((void**)&w4t, g_w4t);
    float* bias4; cudaGetSymbolAddress((void**)&bias4, g_bias4);
    float* wpT;   cudaGetSymbolAddress((void**)&wpT, g_wprojT);

    static int smem_set = 0;
    const int FLASH_SMEM = FL_TOT * 4;
    if (!smem_set) {
        cudaFuncSetAttribute(flash_kernel,
                             cudaFuncAttributeMaxDynamicSharedMemorySize,
                             FLASH_SMEM);
        smem_set = 1;
    }

    // 1. GroupNorm stats
    gnstat_kernel<<<B_ * 32, 256>>>(x, gamma, beta);

    // 2. Weight preps (affine folded into k-major weights + bias vector)
    prep_wqkvT<<<dim3(24, 8, B_), 256>>>(w_qkv);
    prep_bias<<<dim3(96, B_), 256>>>(w_qkv);
    prep_projT<<<dim3(8, 8), 256>>>(w_proj);

    // 3. QKV GEMM (plain GEMM on raw x; V -> g_vt transposed)
    {
        dim3 grid(S_ / 64, (3 * C_) / 128, B_);   // 16 x 6 x 4 = 384
        gemm_cp<true, 128, 8><<<grid, 256>>>(w4t, x, qkv, bias4, nullptr, 3 * C_);
    }

    // 4. Fused flash attention
    {
        dim3 grid(S_ / 128, B_ * HEADS_);
        flash_kernel<<<grid, 256, FLASH_SMEM>>>();
    }

    // 5. Proj + bias + residual
    {
        dim3 grid(S_ / 64, C_ / 64, B_);          // 16 x 4 x 4 = 256
        gemm_cp<false, 64, 4><<<grid, 256>>>(wpT, att, out, b_proj, x, C_);
    }
}